// round 2
// baseline (speedup 1.0000x reference)
#include <cuda_runtime.h>
#include <cstdint>

// ---------------- problem constants ----------------
#define VOCAB 32000
#define EMB   64
#define BATCH 4
#define SEQ   2048
#define MROWS (BATCH * SEQ)   // 8192

// GEMM tiling
#define BM 128
#define BN 128
#define APITCH 68      // floats, conflict-free fragment LDS
#define SPITCH 132     // floats, epilogue staging pitch

// SMEM layout (bytes)
#define SOFF_A    0
#define SZ_A      (BM * APITCH * 4)            // 34816
#define SOFF_B    SZ_A
#define SZ_B      (BN * APITCH * 4)            // 34816
#define SOFF_BIAS (SOFF_B + SZ_B)              // 69632
#define SMEM_SZ   (SOFF_BIAS + 512)            // 70144 -> 2 CTAs/SM
// epilogue stage aliases [0, 128*132*4=67584) over A+B region

// device scratch
__device__ float g_A[MROWS * EMB];       // prefix means, tf32-rounded
__device__ float g_Wt[VOCAB * EMB];      // W, tf32-rounded

// ---------------- helpers ----------------
__device__ __forceinline__ uint32_t f2tf32(float x) {
    uint32_t u;
    asm("cvt.rna.tf32.f32 %0, %1;" : "=r"(u) : "f"(x));
    return u;
}

__device__ __forceinline__ void mma_tf32(float c[4],
                                         uint32_t a0, uint32_t a1, uint32_t a2, uint32_t a3,
                                         uint32_t b0, uint32_t b1) {
    asm volatile(
        "mma.sync.aligned.m16n8k8.row.col.f32.tf32.tf32.f32 "
        "{%0,%1,%2,%3}, {%4,%5,%6,%7}, {%8,%9}, {%0,%1,%2,%3};"
        : "+f"(c[0]), "+f"(c[1]), "+f"(c[2]), "+f"(c[3])
        : "r"(a0), "r"(a1), "r"(a2), "r"(a3), "r"(b0), "r"(b1));
}

// ---------------- kernel 0: W -> tf32-rounded copy ----------------
__global__ void __launch_bounds__(256) wprep_kernel(const float* __restrict__ W) {
    const int i = blockIdx.x * 256 + threadIdx.x;   // float4 index, 512000 total
    float4 v = reinterpret_cast<const float4*>(W)[i];
    v.x = __uint_as_float(f2tf32(v.x));
    v.y = __uint_as_float(f2tf32(v.y));
    v.z = __uint_as_float(f2tf32(v.z));
    v.w = __uint_as_float(f2tf32(v.w));
    reinterpret_cast<float4*>(g_Wt)[i] = v;
}

// ---------------- kernel 1: gather + causal prefix mean (tf32-rounded) ----------------
__global__ void __launch_bounds__(512) prefix_kernel(const float* __restrict__ emb,
                                                     const int* __restrict__ x) {
    __shared__ float ebuf[64 * 64];
    const int b = blockIdx.x;
    const int t = threadIdx.x;
    const int i = t >> 3;     // position in chunk
    const int q = t & 7;      // feature octet
    float run = 0.0f;

    for (int c = 0; c < SEQ / 64; ++c) {
        const int p0 = c * 64;
        __syncthreads();
        const int idx = x[b * SEQ + p0 + i];
        const float4* src = reinterpret_cast<const float4*>(emb + (size_t)idx * EMB) + q * 2;
        float4 v0 = src[0];
        float4 v1 = src[1];
        *reinterpret_cast<float4*>(ebuf + i * 64 + q * 8)     = v0;
        *reinterpret_cast<float4*>(ebuf + i * 64 + q * 8 + 4) = v1;
        __syncthreads();
        if (t < 64) {
            #pragma unroll 8
            for (int p = 0; p < 64; ++p) {
                run += ebuf[p * 64 + t];
                const float inv = __fdividef(1.0f, (float)(p0 + p + 1));
                g_A[(size_t)(b * SEQ + p0 + p) * EMB + t] =
                    __uint_as_float(f2tf32(run * inv));
            }
        }
    }
}

// ---------------- kernel 2: tf32 mma.sync GEMM + bias ----------------
// out[m, n] = sum_k A[m,k] * W[n,k] + bias[n]
__global__ void __launch_bounds__(256, 2) gemm_kernel(const float* __restrict__ bias,
                                                      float* __restrict__ out) {
    extern __shared__ char smem[];
    float* As = reinterpret_cast<float*>(smem + SOFF_A);
    float* Bs = reinterpret_cast<float*>(smem + SOFF_B);
    float* sbias = reinterpret_cast<float*>(smem + SOFF_BIAS);
    float* stg = reinterpret_cast<float*>(smem);   // aliases As/Bs after mainloop

    const int tid  = threadIdx.x;
    const int wid  = tid >> 5;
    const int lane = tid & 31;
    const int gid  = lane >> 2;   // 0..7
    const int tig  = lane & 3;    // 0..3
    const int mw   = wid >> 2;    // warp M index 0..1
    const int nw   = wid & 3;     // warp N index 0..3
    const int n0 = blockIdx.x * BN;
    const int m0 = blockIdx.y * BM;

    // --- stage A tile [128 x 64] ---
    {
        const float4* Af = reinterpret_cast<const float4*>(g_A);
        #pragma unroll
        for (int it = 0; it < 8; ++it) {
            const int lin = it * 256 + tid;   // 0..2047
            const int r = lin >> 4;
            const int f4 = lin & 15;
            float4 v = Af[(size_t)(m0 + r) * 16 + f4];
            *reinterpret_cast<float4*>(As + r * APITCH + f4 * 4) = v;
        }
    }
    // --- stage B tile = Wt rows [n0, n0+128) ---
    {
        const float4* Bf = reinterpret_cast<const float4*>(g_Wt);
        #pragma unroll
        for (int it = 0; it < 8; ++it) {
            const int lin = it * 256 + tid;
            const int r = lin >> 4;
            const int f4 = lin & 15;
            float4 v = Bf[(size_t)(n0 + r) * 16 + f4];
            *reinterpret_cast<float4*>(Bs + r * APITCH + f4 * 4) = v;
        }
    }
    if (tid < 32) {
        reinterpret_cast<float4*>(sbias)[tid] =
            reinterpret_cast<const float4*>(bias)[n0 / 4 + tid];
    }
    __syncthreads();

    // --- mainloop: 8 k-steps of 8, warp tile 64x32 (4 Mtiles x 4 Ntiles) ---
    float acc[4][4][4];
    #pragma unroll
    for (int mt = 0; mt < 4; ++mt)
        #pragma unroll
        for (int nt = 0; nt < 4; ++nt)
            #pragma unroll
            for (int r = 0; r < 4; ++r) acc[mt][nt][r] = 0.0f;

    #pragma unroll
    for (int ks = 0; ks < 8; ++ks) {
        const int k0 = ks * 8;
        uint32_t a[4][4];
        #pragma unroll
        for (int mt = 0; mt < 4; ++mt) {
            const float* ap = As + (mw * 64 + mt * 16 + gid) * APITCH + k0 + tig;
            a[mt][0] = __float_as_uint(ap[0]);
            a[mt][1] = __float_as_uint(ap[8 * APITCH]);
            a[mt][2] = __float_as_uint(ap[4]);
            a[mt][3] = __float_as_uint(ap[8 * APITCH + 4]);
        }
        uint32_t bb[4][2];
        #pragma unroll
        for (int nt = 0; nt < 4; ++nt) {
            const float* bp = Bs + (nw * 32 + nt * 8 + gid) * APITCH + k0 + tig;
            bb[nt][0] = __float_as_uint(bp[0]);
            bb[nt][1] = __float_as_uint(bp[4]);
        }
        #pragma unroll
        for (int mt = 0; mt < 4; ++mt)
            #pragma unroll
            for (int nt = 0; nt < 4; ++nt)
                mma_tf32(acc[mt][nt], a[mt][0], a[mt][1], a[mt][2], a[mt][3],
                         bb[nt][0], bb[nt][1]);
    }

    __syncthreads();   // As/Bs dead; reuse as staging

    // --- stage accumulators (fragment layout -> row-major tile) ---
    #pragma unroll
    for (int mt = 0; mt < 4; ++mt) {
        #pragma unroll
        for (int nt = 0; nt < 4; ++nt) {
            const int r0 = mw * 64 + mt * 16 + gid;
            const int cc = nw * 32 + nt * 8 + 2 * tig;
            float2 lo = make_float2(acc[mt][nt][0], acc[mt][nt][1]);
            float2 hi = make_float2(acc[mt][nt][2], acc[mt][nt][3]);
            *reinterpret_cast<float2*>(stg + r0 * SPITCH + cc) = lo;
            *reinterpret_cast<float2*>(stg + (r0 + 8) * SPITCH + cc) = hi;
        }
    }
    __syncthreads();

    // --- coalesced output: warp w owns rows [w*16, w*16+16), full 128-col rows ---
    float4 bv = *reinterpret_cast<const float4*>(sbias + lane * 4);
    #pragma unroll
    for (int rr = 0; rr < 16; ++rr) {
        const int r = wid * 16 + rr;
        float4 v = *reinterpret_cast<const float4*>(stg + r * SPITCH + lane * 4);
        v.x += bv.x; v.y += bv.y; v.z += bv.z; v.w += bv.w;
        *reinterpret_cast<float4*>(out + (size_t)(m0 + r) * VOCAB + n0 + lane * 4) = v;
    }
}

// ---------------- launch ----------------
extern "C" void kernel_launch(void* const* d_in, const int* in_sizes, int n_in,
                              void* d_out, int out_size) {
    const float* emb  = (const float*)d_in[0];   // [32000, 64] f32
    const float* Wm   = (const float*)d_in[1];   // [32000, 64] f32
    const float* bias = (const float*)d_in[2];   // [32000] f32
    const int*   x    = (const int*)d_in[3];     // [4, 2048] i32
    float* out = (float*)d_out;                  // [4, 2048, 32000] f32

    wprep_kernel<<<(VOCAB * EMB / 4) / 256, 256>>>(Wm);   // 2000 blocks
    prefix_kernel<<<BATCH, 512>>>(emb, x);

    cudaFuncSetAttribute(gemm_kernel, cudaFuncAttributeMaxDynamicSharedMemorySize, SMEM_SZ);
    dim3 grid(VOCAB / BN, MROWS / BM);   // (250, 64)
    gemm_kernel<<<grid, 256, SMEM_SZ>>>(bias, out);
}

// round 3
// speedup vs baseline: 1.3130x; 1.3130x over previous
#include <cuda_runtime.h>
#include <cstdint>

// ---------------- problem constants ----------------
#define VOCAB 32000
#define EMB   64
#define BATCH 4
#define SEQ   2048
#define MROWS (BATCH * SEQ)   // 8192

// GEMM tiling
#define BM 128
#define BN 128
#define APITCH 68                    // floats; conflict-free fragment LDS
#define TILE_BYTES (128 * APITCH * 4)  // 34816

// smem: B tile + double-buffered A tiles
#define SOFF_B  0
#define SOFF_A0 TILE_BYTES
#define SOFF_A1 (2 * TILE_BYTES)
#define SMEM_SZ (3 * TILE_BYTES)     // 104448 -> 2 CTAs/SM

// device scratch
__device__ float g_A[MROWS * EMB];        // prefix means, tf32-rounded
__device__ float g_Wt[VOCAB * EMB];       // W, tf32-rounded
__device__ float g_csum[BATCH * 32 * EMB];
__device__ float g_coff[BATCH * 32 * EMB];

// ---------------- helpers ----------------
__device__ __forceinline__ uint32_t smem_u32(const void* p) {
    uint32_t a;
    asm("{ .reg .u64 t; cvta.to.shared.u64 t, %1; cvt.u32.u64 %0, t; }" : "=r"(a) : "l"(p));
    return a;
}
__device__ __forceinline__ float f2tf32f(float x) {
    uint32_t u;
    asm("cvt.rna.tf32.f32 %0, %1;" : "=r"(u) : "f"(x));
    return __uint_as_float(u);
}
__device__ __forceinline__ void mma_tf32(float c[4],
                                         uint32_t a0, uint32_t a1, uint32_t a2, uint32_t a3,
                                         uint32_t b0, uint32_t b1) {
    asm volatile(
        "mma.sync.aligned.m16n8k8.row.col.f32.tf32.tf32.f32 "
        "{%0,%1,%2,%3}, {%4,%5,%6,%7}, {%8,%9}, {%0,%1,%2,%3};"
        : "+f"(c[0]), "+f"(c[1]), "+f"(c[2]), "+f"(c[3])
        : "r"(a0), "r"(a1), "r"(a2), "r"(a3), "r"(b0), "r"(b1));
}
#define CP_ASYNC16(saddr, gptr) \
    asm volatile("cp.async.cg.shared.global [%0], [%1], 16;" :: "r"(saddr), "l"(gptr))
#define CP_COMMIT() asm volatile("cp.async.commit_group;" ::: "memory")
#define CP_WAIT(n)  asm volatile("cp.async.wait_group %0;" :: "n"(n) : "memory")

// ---------------- kernel 0: W -> tf32-rounded copy ----------------
__global__ void __launch_bounds__(256) wprep_kernel(const float* __restrict__ W) {
    const int i = blockIdx.x * 256 + threadIdx.x;   // float4 index
    float4 v = reinterpret_cast<const float4*>(W)[i];
    v.x = f2tf32f(v.x); v.y = f2tf32f(v.y); v.z = f2tf32f(v.z); v.w = f2tf32f(v.w);
    reinterpret_cast<float4*>(g_Wt)[i] = v;
}

// ---------------- prefix phase 1: chunk-local gather + scan (unscaled) ----------------
__global__ void __launch_bounds__(512) p1_kernel(const float* __restrict__ emb,
                                                 const int* __restrict__ x) {
    __shared__ float ebuf[64 * 64];
    const int c = blockIdx.x, b = blockIdx.y;
    const int t = threadIdx.x;
    const int i = t >> 3, q = t & 7;
    const int p0 = c * 64;
    const int idx = x[b * SEQ + p0 + i];
    const float4* src = reinterpret_cast<const float4*>(emb + (size_t)idx * EMB) + q * 2;
    float4 v0 = src[0];
    float4 v1 = src[1];
    *reinterpret_cast<float4*>(ebuf + i * 64 + q * 8)     = v0;
    *reinterpret_cast<float4*>(ebuf + i * 64 + q * 8 + 4) = v1;
    __syncthreads();
    if (t < 64) {
        float run = 0.0f;
        #pragma unroll 8
        for (int p = 0; p < 64; ++p) {
            run += ebuf[p * 64 + t];
            g_A[(size_t)(b * SEQ + p0 + p) * EMB + t] = run;
        }
        g_csum[(b * 32 + c) * EMB + t] = run;
    }
}

// ---------------- prefix phase 2: per-batch exclusive scan of chunk sums ----------------
__global__ void __launch_bounds__(64) p2_kernel() {
    const int b = blockIdx.x, e = threadIdx.x;
    float s[32];
    #pragma unroll
    for (int c = 0; c < 32; ++c) s[c] = g_csum[(b * 32 + c) * EMB + e];
    float off = 0.0f;
    #pragma unroll
    for (int c = 0; c < 32; ++c) {
        g_coff[(b * 32 + c) * EMB + e] = off;
        off += s[c];
    }
}

// ---------------- prefix phase 3: apply offsets, scale by 1/(p+1), tf32-round ----------------
__global__ void __launch_bounds__(512) p3_kernel() {
    const int c = blockIdx.x, b = blockIdx.y;
    const int t = threadIdx.x;
    const int i = t >> 3, q = t & 7;
    const int p = c * 64 + i;
    const float inv = __fdividef(1.0f, (float)(p + 1));
    float* base = g_A + (size_t)(b * SEQ + p) * EMB + q * 8;
    const float* obase = g_coff + (size_t)(b * 32 + c) * EMB + q * 8;
    float4 a0 = *reinterpret_cast<float4*>(base);
    float4 a1 = *reinterpret_cast<float4*>(base + 4);
    float4 o0 = *reinterpret_cast<const float4*>(obase);
    float4 o1 = *reinterpret_cast<const float4*>(obase + 4);
    a0.x = f2tf32f((a0.x + o0.x) * inv);
    a0.y = f2tf32f((a0.y + o0.y) * inv);
    a0.z = f2tf32f((a0.z + o0.z) * inv);
    a0.w = f2tf32f((a0.w + o0.w) * inv);
    a1.x = f2tf32f((a1.x + o1.x) * inv);
    a1.y = f2tf32f((a1.y + o1.y) * inv);
    a1.z = f2tf32f((a1.z + o1.z) * inv);
    a1.w = f2tf32f((a1.w + o1.w) * inv);
    *reinterpret_cast<float4*>(base)     = a0;
    *reinterpret_cast<float4*>(base + 4) = a1;
}

// ---------------- GEMM: persistent N-tile CTA, double-buffered A, direct epilogue ----------------
// out[m, n] = sum_k A[m,k] * W[n,k] + bias[n]
__global__ void __launch_bounds__(256, 2) gemm_kernel(const float* __restrict__ bias,
                                                      float* __restrict__ out) {
    extern __shared__ char smem[];
    float* Bs  = reinterpret_cast<float*>(smem + SOFF_B);
    float* Abuf0 = reinterpret_cast<float*>(smem + SOFF_A0);
    float* Abuf1 = reinterpret_cast<float*>(smem + SOFF_A1);

    const int tid  = threadIdx.x;
    const int wid  = tid >> 5;
    const int lane = tid & 31;
    const int gid  = lane >> 2;   // 0..7
    const int tig  = lane & 3;    // 0..3
    const int mw   = wid >> 2;    // warp M index 0..1
    const int nw   = wid & 3;     // warp N index 0..3
    const int n0   = blockIdx.x * BN;
    const int yb   = blockIdx.y;  // 0..7, M-tile group

    const uint32_t sB  = smem_u32(Bs);
    const uint32_t sA0 = smem_u32(Abuf0);
    const uint32_t sA1 = smem_u32(Abuf1);

    // staging decomposition: 2048 float4 per tile, 8 per thread
    const int sr  = tid >> 1;                 // base row block helper (unused directly)
    (void)sr;

    // bias -> registers (per-thread cols for each nt)
    float bias_r[4][2];
    #pragma unroll
    for (int nt = 0; nt < 4; ++nt) {
        float2 bv = *reinterpret_cast<const float2*>(bias + n0 + nw * 32 + nt * 8 + 2 * tig);
        bias_r[nt][0] = bv.x;
        bias_r[nt][1] = bv.y;
    }

    // issue B tile + A tile j=0
    {
        const float* gB = g_Wt + (size_t)n0 * EMB;
        #pragma unroll
        for (int it = 0; it < 8; ++it) {
            const int lin = it * 256 + tid;
            const int r = lin >> 4, f4 = lin & 15;
            CP_ASYNC16(sB + (uint32_t)(r * APITCH + f4 * 4) * 4, gB + r * EMB + f4 * 4);
        }
        const float* gA = g_A + (size_t)(yb * BM) * EMB;
        #pragma unroll
        for (int it = 0; it < 8; ++it) {
            const int lin = it * 256 + tid;
            const int r = lin >> 4, f4 = lin & 15;
            CP_ASYNC16(sA0 + (uint32_t)(r * APITCH + f4 * 4) * 4, gA + r * EMB + f4 * 4);
        }
        CP_COMMIT();
    }

    #pragma unroll 1
    for (int j = 0; j < 8; ++j) {
        // prefetch A[j+1] into the other buffer
        if (j < 7) {
            const uint32_t sdst = (j & 1) ? sA0 : sA1;
            const float* gA = g_A + (size_t)((yb + (j + 1) * 8) * BM) * EMB;
            #pragma unroll
            for (int it = 0; it < 8; ++it) {
                const int lin = it * 256 + tid;
                const int r = lin >> 4, f4 = lin & 15;
                CP_ASYNC16(sdst + (uint32_t)(r * APITCH + f4 * 4) * 4, gA + r * EMB + f4 * 4);
            }
            CP_COMMIT();
            CP_WAIT(1);   // A[j] (and B) have landed
        } else {
            CP_WAIT(0);
        }
        __syncthreads();

        const float* Ac = (j & 1) ? Abuf1 : Abuf0;

        // ---- mainloop: 8 k-steps, warp tile 64x32 ----
        float acc[4][4][4];
        #pragma unroll
        for (int mt = 0; mt < 4; ++mt)
            #pragma unroll
            for (int nt = 0; nt < 4; ++nt)
                #pragma unroll
                for (int rr = 0; rr < 4; ++rr) acc[mt][nt][rr] = 0.0f;

        #pragma unroll
        for (int ks = 0; ks < 8; ++ks) {
            const int k0 = ks * 8;
            uint32_t a[4][4];
            #pragma unroll
            for (int mt = 0; mt < 4; ++mt) {
                const float* ap = Ac + (mw * 64 + mt * 16 + gid) * APITCH + k0 + tig;
                a[mt][0] = __float_as_uint(ap[0]);
                a[mt][1] = __float_as_uint(ap[8 * APITCH]);
                a[mt][2] = __float_as_uint(ap[4]);
                a[mt][3] = __float_as_uint(ap[8 * APITCH + 4]);
            }
            uint32_t bb[4][2];
            #pragma unroll
            for (int nt = 0; nt < 4; ++nt) {
                const float* bp = Bs + (nw * 32 + nt * 8 + gid) * APITCH + k0 + tig;
                bb[nt][0] = __float_as_uint(bp[0]);
                bb[nt][1] = __float_as_uint(bp[4]);
            }
            #pragma unroll
            for (int mt = 0; mt < 4; ++mt)
                #pragma unroll
                for (int nt = 0; nt < 4; ++nt)
                    mma_tf32(acc[mt][nt], a[mt][0], a[mt][1], a[mt][2], a[mt][3],
                             bb[nt][0], bb[nt][1]);
        }

        __syncthreads();   // A buffer (j&1) free for prefetch next iteration

        // ---- epilogue: direct STG.64 from fragments ----
        const int m0 = (yb + j * 8) * BM;
        #pragma unroll
        for (int mt = 0; mt < 4; ++mt) {
            const int row0 = m0 + mw * 64 + mt * 16 + gid;
            float* orow0 = out + (size_t)row0 * VOCAB + n0;
            #pragma unroll
            for (int nt = 0; nt < 4; ++nt) {
                const int col = nw * 32 + nt * 8 + 2 * tig;
                float2 v0 = make_float2(acc[mt][nt][0] + bias_r[nt][0],
                                        acc[mt][nt][1] + bias_r[nt][1]);
                float2 v1 = make_float2(acc[mt][nt][2] + bias_r[nt][0],
                                        acc[mt][nt][3] + bias_r[nt][1]);
                *reinterpret_cast<float2*>(orow0 + col) = v0;
                *reinterpret_cast<float2*>(orow0 + (size_t)8 * VOCAB + col) = v1;
            }
        }
    }
}

// ---------------- launch ----------------
extern "C" void kernel_launch(void* const* d_in, const int* in_sizes, int n_in,
                              void* d_out, int out_size) {
    const float* emb  = (const float*)d_in[0];   // [32000, 64] f32
    const float* Wm   = (const float*)d_in[1];   // [32000, 64] f32
    const float* bias = (const float*)d_in[2];   // [32000] f32
    const int*   x    = (const int*)d_in[3];     // [4, 2048] i32
    float* out = (float*)d_out;                  // [4, 2048, 32000] f32

    wprep_kernel<<<(VOCAB * EMB / 4) / 256, 256>>>(Wm);
    p1_kernel<<<dim3(32, BATCH), 512>>>(emb, x);
    p2_kernel<<<BATCH, 64>>>();
    p3_kernel<<<dim3(32, BATCH), 512>>>();

    cudaFuncSetAttribute(gemm_kernel, cudaFuncAttributeMaxDynamicSharedMemorySize, SMEM_SZ);
    dim3 grid(VOCAB / BN, 8);   // (250, 8), each CTA does 8 M-tiles
    gemm_kernel<<<grid, 256, SMEM_SZ>>>(bias, out);
}

// round 4
// speedup vs baseline: 1.7533x; 1.3353x over previous
#include <cuda_runtime.h>
#include <cuda_fp16.h>
#include <cstdint>

// ---------------- problem constants ----------------
#define VOCAB 32000
#define EMB   64
#define BATCH 4
#define SEQ   2048
#define MROWS (BATCH * SEQ)   // 8192

// GEMM tiling
#define BM 128
#define BN 128
#define HPITCH 72                        // halves; conflict-free fragment LDS
#define TILE_BYTES (128 * HPITCH * 2)    // 18432

// smem: B tile + double-buffered A tiles
#define SOFF_B  0
#define SOFF_A0 TILE_BYTES
#define SOFF_A1 (2 * TILE_BYTES)
#define SMEM_SZ (3 * TILE_BYTES)         // 55296

// device scratch
__device__ __half g_A[MROWS * EMB];       // prefix means, fp16
__device__ __half g_Wh[VOCAB * EMB];      // W, fp16
__device__ float  g_S[MROWS * EMB];       // fp32 chunk-local prefix sums
__device__ float  g_csum[BATCH * 32 * EMB];
__device__ float  g_coff[BATCH * 32 * EMB];

// ---------------- helpers ----------------
__device__ __forceinline__ uint32_t smem_u32(const void* p) {
    uint32_t a;
    asm("{ .reg .u64 t; cvta.to.shared.u64 t, %1; cvt.u32.u64 %0, t; }" : "=r"(a) : "l"(p));
    return a;
}
__device__ __forceinline__ void mma_f16(float c[4],
                                        uint32_t a0, uint32_t a1, uint32_t a2, uint32_t a3,
                                        uint32_t b0, uint32_t b1) {
    asm volatile(
        "mma.sync.aligned.m16n8k16.row.col.f32.f16.f16.f32 "
        "{%0,%1,%2,%3}, {%4,%5,%6,%7}, {%8,%9}, {%0,%1,%2,%3};"
        : "+f"(c[0]), "+f"(c[1]), "+f"(c[2]), "+f"(c[3])
        : "r"(a0), "r"(a1), "r"(a2), "r"(a3), "r"(b0), "r"(b1));
}
#define CP_ASYNC16(saddr, gptr) \
    asm volatile("cp.async.cg.shared.global [%0], [%1], 16;" :: "r"(saddr), "l"(gptr))
#define CP_COMMIT() asm volatile("cp.async.commit_group;" ::: "memory")
#define CP_WAIT(n)  asm volatile("cp.async.wait_group %0;" :: "n"(n) : "memory")

// ---------------- kernel 0: W -> fp16 copy ----------------
__global__ void __launch_bounds__(256) wprep_kernel(const float* __restrict__ W) {
    const int i = blockIdx.x * 256 + threadIdx.x;  // 8 floats per thread
    const float4* src = reinterpret_cast<const float4*>(W) + i * 2;
    float4 v0 = src[0];
    float4 v1 = src[1];
    __half2 h[4];
    h[0] = __floats2half2_rn(v0.x, v0.y);
    h[1] = __floats2half2_rn(v0.z, v0.w);
    h[2] = __floats2half2_rn(v1.x, v1.y);
    h[3] = __floats2half2_rn(v1.z, v1.w);
    *reinterpret_cast<uint4*>(g_Wh + (size_t)i * 8) = *reinterpret_cast<uint4*>(h);
}

// ---------------- prefix phase 1: chunk-local gather + scan (unscaled fp32) ----------------
__global__ void __launch_bounds__(512) p1_kernel(const float* __restrict__ emb,
                                                 const int* __restrict__ x) {
    __shared__ float ebuf[64 * 64];
    const int c = blockIdx.x, b = blockIdx.y;
    const int t = threadIdx.x;
    const int i = t >> 3, q = t & 7;
    const int p0 = c * 64;
    const int idx = x[b * SEQ + p0 + i];
    const float4* src = reinterpret_cast<const float4*>(emb + (size_t)idx * EMB) + q * 2;
    float4 v0 = src[0];
    float4 v1 = src[1];
    *reinterpret_cast<float4*>(ebuf + i * 64 + q * 8)     = v0;
    *reinterpret_cast<float4*>(ebuf + i * 64 + q * 8 + 4) = v1;
    __syncthreads();
    if (t < 64) {
        float run = 0.0f;
        #pragma unroll 8
        for (int p = 0; p < 64; ++p) {
            run += ebuf[p * 64 + t];
            g_S[(size_t)(b * SEQ + p0 + p) * EMB + t] = run;
        }
        g_csum[(b * 32 + c) * EMB + t] = run;
    }
}

// ---------------- prefix phase 2: per-batch exclusive scan of chunk sums ----------------
__global__ void __launch_bounds__(64) p2_kernel() {
    const int b = blockIdx.x, e = threadIdx.x;
    float off = 0.0f;
    #pragma unroll
    for (int c = 0; c < 32; ++c) {
        g_coff[(b * 32 + c) * EMB + e] = off;
        off += g_csum[(b * 32 + c) * EMB + e];
    }
}

// ---------------- prefix phase 3: apply offsets, scale, fp16-round ----------------
__global__ void __launch_bounds__(512) p3_kernel() {
    const int c = blockIdx.x, b = blockIdx.y;
    const int t = threadIdx.x;
    const int i = t >> 3, q = t & 7;
    const int p = c * 64 + i;
    const float inv = __fdividef(1.0f, (float)(p + 1));
    const float* base  = g_S + (size_t)(b * SEQ + p) * EMB + q * 8;
    const float* obase = g_coff + (size_t)(b * 32 + c) * EMB + q * 8;
    float4 a0 = *reinterpret_cast<const float4*>(base);
    float4 a1 = *reinterpret_cast<const float4*>(base + 4);
    float4 o0 = *reinterpret_cast<const float4*>(obase);
    float4 o1 = *reinterpret_cast<const float4*>(obase + 4);
    __half2 h[4];
    h[0] = __floats2half2_rn((a0.x + o0.x) * inv, (a0.y + o0.y) * inv);
    h[1] = __floats2half2_rn((a0.z + o0.z) * inv, (a0.w + o0.w) * inv);
    h[2] = __floats2half2_rn((a1.x + o1.x) * inv, (a1.y + o1.y) * inv);
    h[3] = __floats2half2_rn((a1.z + o1.z) * inv, (a1.w + o1.w) * inv);
    *reinterpret_cast<uint4*>(g_A + (size_t)(b * SEQ + p) * EMB + q * 8) =
        *reinterpret_cast<uint4*>(h);
}

// ---------------- GEMM: fp16 mma.sync, persistent N-tile CTA, double-buffered A ----------------
// out[m, n] = sum_k A[m,k] * W[n,k] + bias[n]
__global__ void __launch_bounds__(256, 2) gemm_kernel(const float* __restrict__ bias,
                                                      float* __restrict__ out) {
    extern __shared__ char smem[];
    __half* Bs    = reinterpret_cast<__half*>(smem + SOFF_B);
    __half* Abuf0 = reinterpret_cast<__half*>(smem + SOFF_A0);
    __half* Abuf1 = reinterpret_cast<__half*>(smem + SOFF_A1);

    const int tid  = threadIdx.x;
    const int wid  = tid >> 5;
    const int lane = tid & 31;
    const int gid  = lane >> 2;   // 0..7
    const int tig  = lane & 3;    // 0..3
    const int mw   = wid >> 2;    // warp M index 0..1
    const int nw   = wid & 3;     // warp N index 0..3
    const int n0   = blockIdx.x * BN;
    const int yb   = blockIdx.y;  // 0..7

    const uint32_t sB  = smem_u32(Bs);
    const uint32_t sA0 = smem_u32(Abuf0);
    const uint32_t sA1 = smem_u32(Abuf1);

    // bias -> registers
    float bias_r[4][2];
    #pragma unroll
    for (int nt = 0; nt < 4; ++nt) {
        float2 bv = *reinterpret_cast<const float2*>(bias + n0 + nw * 32 + nt * 8 + 2 * tig);
        bias_r[nt][0] = bv.x;
        bias_r[nt][1] = bv.y;
    }

    // issue B tile + A tile j=0 (1024 cp.async x16B per tile; 4 per thread)
    {
        const __half* gB = g_Wh + (size_t)n0 * EMB;
        #pragma unroll
        for (int it = 0; it < 4; ++it) {
            const int lin = it * 256 + tid;
            const int r = lin >> 3, f8 = lin & 7;      // f8: 8-half (16B) chunk
            CP_ASYNC16(sB + (uint32_t)(r * HPITCH + f8 * 8) * 2, gB + r * EMB + f8 * 8);
        }
        const __half* gA = g_A + (size_t)(yb * BM) * EMB;
        #pragma unroll
        for (int it = 0; it < 4; ++it) {
            const int lin = it * 256 + tid;
            const int r = lin >> 3, f8 = lin & 7;
            CP_ASYNC16(sA0 + (uint32_t)(r * HPITCH + f8 * 8) * 2, gA + r * EMB + f8 * 8);
        }
        CP_COMMIT();
    }

    #pragma unroll 1
    for (int j = 0; j < 8; ++j) {
        if (j < 7) {
            const uint32_t sdst = (j & 1) ? sA0 : sA1;
            const __half* gA = g_A + (size_t)((yb + (j + 1) * 8) * BM) * EMB;
            #pragma unroll
            for (int it = 0; it < 4; ++it) {
                const int lin = it * 256 + tid;
                const int r = lin >> 3, f8 = lin & 7;
                CP_ASYNC16(sdst + (uint32_t)(r * HPITCH + f8 * 8) * 2, gA + r * EMB + f8 * 8);
            }
            CP_COMMIT();
            CP_WAIT(1);
        } else {
            CP_WAIT(0);
        }
        __syncthreads();

        const __half* Ac = (j & 1) ? Abuf1 : Abuf0;

        // ---- mainloop: 4 k-steps of 16, warp tile 64x32 ----
        float acc[4][4][4];
        #pragma unroll
        for (int mt = 0; mt < 4; ++mt)
            #pragma unroll
            for (int nt = 0; nt < 4; ++nt)
                #pragma unroll
                for (int rr = 0; rr < 4; ++rr) acc[mt][nt][rr] = 0.0f;

        #pragma unroll
        for (int ks = 0; ks < 4; ++ks) {
            const int k0 = ks * 16;
            uint32_t a[4][4];
            #pragma unroll
            for (int mt = 0; mt < 4; ++mt) {
                const __half* ap = Ac + (mw * 64 + mt * 16 + gid) * HPITCH + k0 + 2 * tig;
                a[mt][0] = *reinterpret_cast<const uint32_t*>(ap);
                a[mt][1] = *reinterpret_cast<const uint32_t*>(ap + 8 * HPITCH);
                a[mt][2] = *reinterpret_cast<const uint32_t*>(ap + 8);
                a[mt][3] = *reinterpret_cast<const uint32_t*>(ap + 8 * HPITCH + 8);
            }
            uint32_t bb[4][2];
            #pragma unroll
            for (int nt = 0; nt < 4; ++nt) {
                const __half* bp = Bs + (nw * 32 + nt * 8 + gid) * HPITCH + k0 + 2 * tig;
                bb[nt][0] = *reinterpret_cast<const uint32_t*>(bp);
                bb[nt][1] = *reinterpret_cast<const uint32_t*>(bp + 8);
            }
            #pragma unroll
            for (int mt = 0; mt < 4; ++mt)
                #pragma unroll
                for (int nt = 0; nt < 4; ++nt)
                    mma_f16(acc[mt][nt], a[mt][0], a[mt][1], a[mt][2], a[mt][3],
                            bb[nt][0], bb[nt][1]);
        }

        __syncthreads();   // all reads of A[j] done before next prefetch overwrites

        // ---- epilogue: direct STG.64 from fragments + bias ----
        const int m0 = (yb + j * 8) * BM;
        #pragma unroll
        for (int mt = 0; mt < 4; ++mt) {
            const int row0 = m0 + mw * 64 + mt * 16 + gid;
            float* orow0 = out + (size_t)row0 * VOCAB + n0;
            #pragma unroll
            for (int nt = 0; nt < 4; ++nt) {
                const int col = nw * 32 + nt * 8 + 2 * tig;
                float2 v0 = make_float2(acc[mt][nt][0] + bias_r[nt][0],
                                        acc[mt][nt][1] + bias_r[nt][1]);
                float2 v1 = make_float2(acc[mt][nt][2] + bias_r[nt][0],
                                        acc[mt][nt][3] + bias_r[nt][1]);
                *reinterpret_cast<float2*>(orow0 + col) = v0;
                *reinterpret_cast<float2*>(orow0 + (size_t)8 * VOCAB + col) = v1;
            }
        }
    }
}

// ---------------- launch ----------------
extern "C" void kernel_launch(void* const* d_in, const int* in_sizes, int n_in,
                              void* d_out, int out_size) {
    const float* emb  = (const float*)d_in[0];   // [32000, 64] f32
    const float* Wm   = (const float*)d_in[1];   // [32000, 64] f32
    const float* bias = (const float*)d_in[2];   // [32000] f32
    const int*   x    = (const int*)d_in[3];     // [4, 2048] i32
    float* out = (float*)d_out;                  // [4, 2048, 32000] f32

    wprep_kernel<<<(VOCAB * EMB / 8) / 256, 256>>>(Wm);   // 1000 blocks
    p1_kernel<<<dim3(32, BATCH), 512>>>(emb, x);
    p2_kernel<<<BATCH, 64>>>();
    p3_kernel<<<dim3(32, BATCH), 512>>>();

    cudaFuncSetAttribute(gemm_kernel, cudaFuncAttributeMaxDynamicSharedMemorySize, SMEM_SZ);
    dim3 grid(VOCAB / BN, 8);   // (250, 8)
    gemm_kernel<<<grid, 256, SMEM_SZ>>>(bias, out);
}